// round 4
// baseline (speedup 1.0000x reference)
#include <cuda_runtime.h>
#include <cuda_bf16.h>

// Problem constants (shapes fixed by the dataset)
#define FGRID 64
#define MAX_N 2000000

// Accumulators + scratch (device globals: allocation-free per harness rules)
__device__ double g_accD;
__device__ double g_accR;
__device__ float4 g_W[MAX_N];   // W[i] = V[i] - V_ref[i], padded to 16B for 1-sector gathers

__global__ void k_init() {
    g_accD = 0.0;
    g_accR = 0.0;
}

__device__ __forceinline__ void block_reduce_atomic(float v, double* acc) {
    #pragma unroll
    for (int o = 16; o; o >>= 1)
        v += __shfl_xor_sync(0xffffffffu, v, o);
    __shared__ float warp_sums[32];
    int lane = threadIdx.x & 31;
    int wid  = threadIdx.x >> 5;
    if (lane == 0) warp_sums[wid] = v;
    __syncthreads();
    if (wid == 0) {
        int nw = (blockDim.x + 31) >> 5;
        float s = (lane < nw) ? warp_sums[lane] : 0.0f;
        #pragma unroll
        for (int o = 16; o; o >>= 1)
            s += __shfl_xor_sync(0xffffffffu, s, o);
        if (lane == 0) atomicAdd(acc, (double)s);
    }
}

// Kernel A: W = V - V_ref  (padded float4), plus trilinear distance-field loss
__global__ void k_vertex(const float* __restrict__ V,
                         const float* __restrict__ Vref,
                         const float* __restrict__ field,
                         int N) {
    float acc = 0.0f;
    for (int i = blockIdx.x * blockDim.x + threadIdx.x; i < N;
         i += gridDim.x * blockDim.x) {
        float vx = V[3 * i + 0];
        float vy = V[3 * i + 1];
        float vz = V[3 * i + 2];
        float rx = Vref[3 * i + 0];
        float ry = Vref[3 * i + 1];
        float rz = Vref[3 * i + 2];
        g_W[i] = make_float4(vx - rx, vy - ry, vz - rz, 0.0f);

        // trilinear sample at (vx,vy,vz), matching reference clip semantics
        float cx = fmaxf(fminf(vx * 63.0f, 62.9999f), 0.0f);
        float cy = fmaxf(fminf(vy * 63.0f, 62.9999f), 0.0f);
        float cz = fmaxf(fminf(vz * 63.0f, 62.9999f), 0.0f);
        int x0 = (int)cx;  float fx = cx - (float)x0;
        int y0 = (int)cy;  float fy = cy - (float)y0;
        int z0 = (int)cz;  float fz = cz - (float)z0;
        int base = x0 * (FGRID * FGRID) + y0 * FGRID + z0;

        float c000 = __ldg(field + base);
        float c001 = __ldg(field + base + 1);
        float c010 = __ldg(field + base + FGRID);
        float c011 = __ldg(field + base + FGRID + 1);
        float c100 = __ldg(field + base + FGRID * FGRID);
        float c101 = __ldg(field + base + FGRID * FGRID + 1);
        float c110 = __ldg(field + base + FGRID * FGRID + FGRID);
        float c111 = __ldg(field + base + FGRID * FGRID + FGRID + 1);

        float c00 = fmaf(fz, c001 - c000, c000);
        float c01 = fmaf(fz, c011 - c010, c010);
        float c10 = fmaf(fz, c101 - c100, c100);
        float c11 = fmaf(fz, c111 - c110, c110);
        float c0  = fmaf(fy, c01 - c00, c00);
        float c1  = fmaf(fy, c11 - c10, c10);
        float d   = fmaf(fx, c1 - c0, c0);

        acc = fmaf(d, d, acc);
    }
    block_reduce_atomic(0.5f * acc, &g_accD);
}

// Kernel B: rigidity loss over edges. E is int32 [M,2] (JAX x64 disabled).
// 2 one-sector float4 gathers per edge; 2-edge unroll for MLP depth.
__global__ void k_edge(const int* __restrict__ E, long long M) {
    float acc = 0.0f;
    const int2* __restrict__ E2 = (const int2*)E;
    long long stride = (long long)gridDim.x * blockDim.x;
    long long i = (long long)blockIdx.x * blockDim.x + threadIdx.x;
    for (; i + stride < M; i += 2 * stride) {
        int2 e0 = __ldg(E2 + i);
        int2 e1 = __ldg(E2 + i + stride);
        float4 a0 = __ldg(&g_W[e0.x]);
        float4 b0 = __ldg(&g_W[e0.y]);
        float4 a1 = __ldg(&g_W[e1.x]);
        float4 b1 = __ldg(&g_W[e1.y]);
        float dx0 = a0.x - b0.x, dy0 = a0.y - b0.y, dz0 = a0.z - b0.z;
        float dx1 = a1.x - b1.x, dy1 = a1.y - b1.y, dz1 = a1.z - b1.z;
        acc += fmaf(dx0, dx0, fmaf(dy0, dy0, dz0 * dz0));
        acc += fmaf(dx1, dx1, fmaf(dy1, dy1, dz1 * dz1));
    }
    if (i < M) {
        int2 e = __ldg(E2 + i);
        float4 a = __ldg(&g_W[e.x]);
        float4 b = __ldg(&g_W[e.y]);
        float dx = a.x - b.x, dy = a.y - b.y, dz = a.z - b.z;
        acc += fmaf(dx, dx, fmaf(dy, dy, dz * dz));
    }
    block_reduce_atomic(0.5f * acc, &g_accR);
}

__global__ void k_final(const float* __restrict__ rig2, float* __restrict__ out) {
    out[0] = (float)(g_accD + (double)rig2[0] * g_accR);
}

extern "C" void kernel_launch(void* const* d_in, const int* in_sizes, int n_in,
                              void* d_out, int out_size) {
    // Resolve inputs by element count (robust to metadata ordering):
    //   E          : 2*M = 24,000,000 (largest)  -- int32 (JAX x64 disabled)
    //   V, V_ref   : 3*N = 6,000,000 each (V first)
    //   dist_field : 64^3 = 262,144
    //   rigidity2  : 1
    const float* V     = nullptr;
    const float* Vref  = nullptr;
    const int*   E     = nullptr;
    const float* field = nullptr;
    const float* rig2  = nullptr;
    long long E_elems = 0;
    int       V_elems = 0;

    int big = 0;
    for (int k = 1; k < n_in; k++)
        if (in_sizes[k] > in_sizes[big]) big = k;
    E = (const int*)d_in[big];
    E_elems = in_sizes[big];

    for (int k = 0; k < n_in; k++) {
        if (k == big) continue;
        if (in_sizes[k] == 1) {
            rig2 = (const float*)d_in[k];
        } else if (in_sizes[k] == FGRID * FGRID * FGRID) {
            field = (const float*)d_in[k];
        } else if (!V) {
            V = (const float*)d_in[k];
            V_elems = in_sizes[k];
        } else {
            Vref = (const float*)d_in[k];
        }
    }

    float* out = (float*)d_out;
    int       N = V_elems / 3;
    long long M = E_elems / 2;

    k_init<<<1, 1>>>();

    int vb = 4096;
    k_vertex<<<vb, 256>>>(V, Vref, field, N);

    int eb = 6144;
    k_edge<<<eb, 256>>>(E, M);

    k_final<<<1, 1>>>(rig2, out);
}